// round 1
// baseline (speedup 1.0000x reference)
#include <cuda_runtime.h>
#include <math.h>

// Problem constants (fixed by the reference): B=2048, S=1, E=1024, H=128, DK=NW=8.
#define B_DIM 2048
#define E_DIM 1024
#define NGROUPS (B_DIM * 128)   // B*H = 262144 groups of 8

// GEMM tiling
#define BM 128
#define BN 64
#define BK 16
#define LDT 18                  // padded smem row stride (conflict-free frag loads)

// Scratch (no cudaMalloc allowed) — __device__ globals.
__device__ float g_v[B_DIM * E_DIM];
__device__ float g_q[B_DIM * E_DIM];

__device__ __forceinline__ unsigned tf32_rna(float x) {
    unsigned r;
    asm("cvt.rna.tf32.f32 %0, %1;" : "=r"(r) : "f"(x));
    return r;
}

__device__ __forceinline__ void split_tf32(float x, float& hi, float& lo) {
    hi = __uint_as_float(tf32_rna(x));
    lo = __uint_as_float(tf32_rna(x - hi));
}

__device__ __forceinline__ void mma8(float* d, const unsigned* a, const unsigned* b) {
    asm volatile(
        "mma.sync.aligned.m16n8k8.row.col.f32.tf32.tf32.f32 "
        "{%0,%1,%2,%3}, {%4,%5,%6,%7}, {%8,%9}, {%0,%1,%2,%3};\n"
        : "+f"(d[0]), "+f"(d[1]), "+f"(d[2]), "+f"(d[3])
        : "r"(a[0]), "r"(a[1]), "r"(a[2]), "r"(a[3]),
          "r"(b[0]), "r"(b[1]));
}

// C[M,N] = A[M,K] * B[N,K]^T (+bias), 3xTF32 split for ~fp32 accuracy.
__global__ void __launch_bounds__(256, 1)
gemm_tf32x3(const float* __restrict__ A, const float* __restrict__ Bm,
            const float* __restrict__ bias, float* __restrict__ C,
            int M, int N, int K)
{
    __shared__ float Ah[BM][LDT], Al[BM][LDT];
    __shared__ float Bh[BN][LDT], Bl[BN][LDT];

    const int tid = threadIdx.x;
    const int bm0 = blockIdx.y * BM;
    const int bn0 = blockIdx.x * BN;
    const int warp = tid >> 5, lane = tid & 31;
    const int wm = (warp & 3) << 5;   // 4 warps along M
    const int wn = (warp >> 2) << 5;  // 2 warps along N
    const int gp = lane >> 2, tg = lane & 3;

    float acc[2][4][4];
#pragma unroll
    for (int mt = 0; mt < 2; mt++)
#pragma unroll
        for (int nt = 0; nt < 4; nt++)
#pragma unroll
            for (int i = 0; i < 4; i++) acc[mt][nt][i] = 0.0f;

    for (int kt = 0; kt < K; kt += BK) {
        // --- load A tile: 128 x 16 floats = 512 float4, 2 per thread
#pragma unroll
        for (int i = 0; i < 2; i++) {
            int idx = tid + (i << 8);
            int r = idx >> 2;
            int c = (idx & 3) << 2;
            float4 v4 = *reinterpret_cast<const float4*>(
                A + (size_t)(bm0 + r) * K + kt + c);
            float h, l;
            split_tf32(v4.x, h, l); Ah[r][c + 0] = h; Al[r][c + 0] = l;
            split_tf32(v4.y, h, l); Ah[r][c + 1] = h; Al[r][c + 1] = l;
            split_tf32(v4.z, h, l); Ah[r][c + 2] = h; Al[r][c + 2] = l;
            split_tf32(v4.w, h, l); Ah[r][c + 3] = h; Al[r][c + 3] = l;
        }
        // --- load B tile: 64 x 16 floats = 256 float4, 1 per thread
        {
            int r = tid >> 2;
            int c = (tid & 3) << 2;
            float4 v4 = *reinterpret_cast<const float4*>(
                Bm + (size_t)(bn0 + r) * K + kt + c);
            float h, l;
            split_tf32(v4.x, h, l); Bh[r][c + 0] = h; Bl[r][c + 0] = l;
            split_tf32(v4.y, h, l); Bh[r][c + 1] = h; Bl[r][c + 1] = l;
            split_tf32(v4.z, h, l); Bh[r][c + 2] = h; Bl[r][c + 2] = l;
            split_tf32(v4.w, h, l); Bh[r][c + 3] = h; Bl[r][c + 3] = l;
        }
        __syncthreads();

#pragma unroll
        for (int kk = 0; kk < BK; kk += 8) {
            unsigned ah[2][4], al[2][4], bh[4][2], bl[4][2];
#pragma unroll
            for (int mt = 0; mt < 2; mt++) {
                int r0 = wm + (mt << 4) + gp;
                ah[mt][0] = __float_as_uint(Ah[r0    ][kk + tg]);
                ah[mt][1] = __float_as_uint(Ah[r0 + 8][kk + tg]);
                ah[mt][2] = __float_as_uint(Ah[r0    ][kk + tg + 4]);
                ah[mt][3] = __float_as_uint(Ah[r0 + 8][kk + tg + 4]);
                al[mt][0] = __float_as_uint(Al[r0    ][kk + tg]);
                al[mt][1] = __float_as_uint(Al[r0 + 8][kk + tg]);
                al[mt][2] = __float_as_uint(Al[r0    ][kk + tg + 4]);
                al[mt][3] = __float_as_uint(Al[r0 + 8][kk + tg + 4]);
            }
#pragma unroll
            for (int nt = 0; nt < 4; nt++) {
                int n0 = wn + (nt << 3) + gp;
                bh[nt][0] = __float_as_uint(Bh[n0][kk + tg]);
                bh[nt][1] = __float_as_uint(Bh[n0][kk + tg + 4]);
                bl[nt][0] = __float_as_uint(Bl[n0][kk + tg]);
                bl[nt][1] = __float_as_uint(Bl[n0][kk + tg + 4]);
            }
#pragma unroll
            for (int mt = 0; mt < 2; mt++)
#pragma unroll
                for (int nt = 0; nt < 4; nt++) {
                    mma8(acc[mt][nt], ah[mt], bh[nt]);  // hi*hi
                    mma8(acc[mt][nt], ah[mt], bl[nt]);  // hi*lo
                    mma8(acc[mt][nt], al[mt], bh[nt]);  // lo*hi
                }
        }
        __syncthreads();
    }

    // epilogue
#pragma unroll
    for (int mt = 0; mt < 2; mt++)
#pragma unroll
        for (int nt = 0; nt < 4; nt++) {
            int m = bm0 + wm + (mt << 4) + gp;
            int n = bn0 + wn + (nt << 3) + (tg << 1);
            float b0 = 0.0f, b1 = 0.0f;
            if (bias) { b0 = bias[n]; b1 = bias[n + 1]; }
            C[(size_t)m * N + n]           = acc[mt][nt][0] + b0;
            C[(size_t)m * N + n + 1]       = acc[mt][nt][1] + b1;
            C[(size_t)(m + 8) * N + n]     = acc[mt][nt][2] + b0;
            C[(size_t)(m + 8) * N + n + 1] = acc[mt][nt][3] + b1;
        }
}

// Closed-form quantum layer:
//   theta_j = v[g,j] + rx[j];  c_j = cos(theta_j)
//   q[g,0] = c1*c2*...*c7;  q[g,w] = c0*...*cw  (w>=1)
__global__ void quantum_kernel(const float* __restrict__ v,
                               const float* __restrict__ rx,
                               float* __restrict__ q, int n)
{
    int g = blockIdx.x * blockDim.x + threadIdx.x;
    if (g >= n) return;
    const float4* vp = reinterpret_cast<const float4*>(v + (size_t)g * 8);
    float4 v0 = vp[0], v1 = vp[1];

    float c0 = cosf(v0.x + __ldg(rx + 0));
    float c1 = cosf(v0.y + __ldg(rx + 1));
    float c2 = cosf(v0.z + __ldg(rx + 2));
    float c3 = cosf(v0.w + __ldg(rx + 3));
    float c4 = cosf(v1.x + __ldg(rx + 4));
    float c5 = cosf(v1.y + __ldg(rx + 5));
    float c6 = cosf(v1.z + __ldg(rx + 6));
    float c7 = cosf(v1.w + __ldg(rx + 7));

    float p1 = c0 * c1;
    float p2 = p1 * c2;
    float p3 = p2 * c3;
    float p4 = p3 * c4;
    float p5 = p4 * c5;
    float p6 = p5 * c6;
    float p7 = p6 * c7;
    float p0 = ((c1 * c2) * (c3 * c4)) * ((c5 * c6) * c7);

    float4* qp = reinterpret_cast<float4*>(q + (size_t)g * 8);
    qp[0] = make_float4(p0, p1, p2, p3);
    qp[1] = make_float4(p4, p5, p6, p7);
}

extern "C" void kernel_launch(void* const* d_in, const int* in_sizes, int n_in,
                              void* d_out, int out_size)
{
    const float* x  = (const float*)d_in[0];
    // d_in[1]=wq, d_in[2]=wk are provably unused (S==1 -> softmax==1 -> out==v)
    const float* wv = (const float*)d_in[3];
    const float* wc = (const float*)d_in[4];
    const float* bc = (const float*)d_in[5];
    const float* rx = (const float*)d_in[6];
    float* out = (float*)d_out;

    float *v_buf, *q_buf;
    cudaGetSymbolAddress((void**)&v_buf, g_v);
    cudaGetSymbolAddress((void**)&q_buf, g_q);

    dim3 grid(E_DIM / BN, B_DIM / BM);
    dim3 blk(256);

    // v = x @ wv^T
    gemm_tf32x3<<<grid, blk>>>(x, wv, nullptr, v_buf, B_DIM, E_DIM, E_DIM);
    // closed-form quantum layer
    quantum_kernel<<<NGROUPS / 256, 256>>>(v_buf, rx, q_buf, NGROUPS);
    // out = q @ wc^T + bc
    gemm_tf32x3<<<grid, blk>>>(q_buf, wc, bc, out, B_DIM, E_DIM, E_DIM);
}

// round 2
// speedup vs baseline: 3.4052x; 3.4052x over previous
#include <cuda_runtime.h>
#include <cuda_bf16.h>
#include <math.h>
#include <stdint.h>

// Fixed problem shape: B=2048, S=1, E=1024, H=128, DK=NW=8.
#define M_DIM 2048
#define E_DIM 1024
#define NGROUPS (M_DIM * 128)

#define BM 128
#define BN 128
#define BK 32
#define NKITER (E_DIM / BK)

// -------- device scratch (no cudaMalloc allowed) --------
__device__ __nv_bfloat16 g_xh[M_DIM * E_DIM];
__device__ __nv_bfloat16 g_xl[M_DIM * E_DIM];
__device__ __nv_bfloat16 g_wvh[E_DIM * E_DIM];
__device__ __nv_bfloat16 g_wvl[E_DIM * E_DIM];
__device__ __nv_bfloat16 g_wch[E_DIM * E_DIM];
__device__ __nv_bfloat16 g_wcl[E_DIM * E_DIM];
__device__ __nv_bfloat16 g_qh[M_DIM * E_DIM];
__device__ __nv_bfloat16 g_ql[M_DIM * E_DIM];
__device__ float g_v[M_DIM * E_DIM];

// -------- helpers --------
__device__ __forceinline__ void split_bf(float x, __nv_bfloat16& h, __nv_bfloat16& l) {
    h = __float2bfloat16(x);
    l = __float2bfloat16(x - __bfloat162float(h));
}

struct alignas(8) bf4 { __nv_bfloat16 a, b, c, d; };

#define CP_ASYNC16(dst, src) \
    asm volatile("cp.async.cg.shared.global [%0], [%1], 16;\n" :: "r"(dst), "l"(src))

#define LDSM4(r, addr) \
    asm volatile("ldmatrix.sync.aligned.m8n8.x4.shared.b16 {%0,%1,%2,%3}, [%4];" \
        : "=r"((r)[0]), "=r"((r)[1]), "=r"((r)[2]), "=r"((r)[3]) : "r"(addr))

__device__ __forceinline__ void mma_bf16(float* d, const uint32_t* a, const uint32_t* b) {
    asm volatile(
        "mma.sync.aligned.m16n8k16.row.col.f32.bf16.bf16.f32 "
        "{%0,%1,%2,%3}, {%4,%5,%6,%7}, {%8,%9}, {%0,%1,%2,%3};\n"
        : "+f"(d[0]), "+f"(d[1]), "+f"(d[2]), "+f"(d[3])
        : "r"(a[0]), "r"(a[1]), "r"(a[2]), "r"(a[3]), "r"(b[0]), "r"(b[1]));
}

// -------- fp32 -> (hi, lo) bf16 split, vectorized --------
__global__ void split_kernel(const float* __restrict__ src,
                             __nv_bfloat16* __restrict__ hi,
                             __nv_bfloat16* __restrict__ lo, int n4)
{
    int i = blockIdx.x * blockDim.x + threadIdx.x;
    if (i >= n4) return;
    float4 v = reinterpret_cast<const float4*>(src)[i];
    bf4 h4, l4;
    split_bf(v.x, h4.a, l4.a);
    split_bf(v.y, h4.b, l4.b);
    split_bf(v.z, h4.c, l4.c);
    split_bf(v.w, h4.d, l4.d);
    reinterpret_cast<bf4*>(hi)[i] = h4;
    reinterpret_cast<bf4*>(lo)[i] = l4;
}

// -------- GEMM: C[M,N] = A[M,K] @ B[N,K]^T (+bias), 3xBF16 split --------
// A,B given as (hi,lo) bf16. M=2048, N=K=1024 hardcoded.
__global__ void __launch_bounds__(256, 1)
gemm_bf16x3(const __nv_bfloat16* __restrict__ Ah, const __nv_bfloat16* __restrict__ Al,
            const __nv_bfloat16* __restrict__ Bh, const __nv_bfloat16* __restrict__ Bl,
            const float* __restrict__ bias, float* __restrict__ C)
{
    extern __shared__ char smem[];
    // layout (bytes): A: [buf][split][128 rows][4 swizzled 16B chunks] = 2*2*8192 = 32768
    //                 B: +32768, same shape
    const uint32_t sbase = (uint32_t)__cvta_generic_to_shared(smem);

    const int tid  = threadIdx.x;
    const int lane = tid & 31;
    const int warp = tid >> 5;
    const int bm0 = blockIdx.y * BM;
    const int bn0 = blockIdx.x * BN;
    const int wm = (warp & 1) * 64;    // 2 warps along M, warp tile 64
    const int wn = (warp >> 1) * 32;   // 4 warps along N, warp tile 32

    // ---- cp.async per-thread offsets (pass 0 covers rows 0..63, pass 1 adds 64) ----
    const int r0 = tid >> 2;           // 0..63
    const int c  = tid & 3;            // 16B chunk
    const uint32_t sw = (uint32_t)(c ^ ((r0 >> 1) & 3));
    const uint32_t sd0 = (uint32_t)r0 * 64 + sw * 16;       // within-tile dst bytes
    const size_t gA0 = (size_t)(bm0 + r0) * E_DIM + c * 8;  // element offsets
    const size_t gB0 = (size_t)(bn0 + r0) * E_DIM + c * 8;

    // ---- ldmatrix per-thread addresses (buf 0, ks 0) ----
    const int arow = ((lane >> 3) & 1) * 8 + (lane & 7);
    const int achk = (lane >> 4) & 1;
    uint32_t addrA[2][4];   // [split][mt]
#pragma unroll
    for (int mt = 0; mt < 4; mt++) {
        int rA = wm + mt * 16 + arow;
        uint32_t off = (uint32_t)rA * 64 + (uint32_t)((achk ^ ((rA >> 1) & 3)) * 16);
#pragma unroll
        for (int s = 0; s < 2; s++)
            addrA[s][mt] = sbase + (uint32_t)s * 8192 + off;
    }
    const int brow = ((lane >> 4) & 1) * 8 + (lane & 7);
    const int bchk = (lane >> 3) & 1;
    uint32_t addrB[2][2];   // [split][pair] (each x4 covers 2 n-tiles)
#pragma unroll
    for (int p = 0; p < 2; p++) {
        int rB = wn + p * 16 + brow;
        uint32_t off = (uint32_t)rB * 64 + (uint32_t)((bchk ^ ((rB >> 1) & 3)) * 16);
#pragma unroll
        for (int s = 0; s < 2; s++)
            addrB[s][p] = sbase + 32768u + (uint32_t)s * 8192 + off;
    }

    float acc[4][4][4];
#pragma unroll
    for (int mt = 0; mt < 4; mt++)
#pragma unroll
        for (int nt = 0; nt < 4; nt++)
#pragma unroll
            for (int i = 0; i < 4; i++) acc[mt][nt][i] = 0.0f;

    // tile loader: 8 x cp.async of 16B per thread
    auto load_tile = [&](int buf, int kt) {
        uint32_t aB = sbase + (uint32_t)buf * 16384;
        uint32_t bB = aB + 32768u;
        CP_ASYNC16(aB + sd0,              Ah + gA0 + kt);
        CP_ASYNC16(aB + sd0 + 4096,       Ah + gA0 + 64 * E_DIM + kt);
        CP_ASYNC16(aB + 8192 + sd0,       Al + gA0 + kt);
        CP_ASYNC16(aB + 8192 + sd0 + 4096, Al + gA0 + 64 * E_DIM + kt);
        CP_ASYNC16(bB + sd0,              Bh + gB0 + kt);
        CP_ASYNC16(bB + sd0 + 4096,       Bh + gB0 + 64 * E_DIM + kt);
        CP_ASYNC16(bB + 8192 + sd0,       Bl + gB0 + kt);
        CP_ASYNC16(bB + 8192 + sd0 + 4096, Bl + gB0 + 64 * E_DIM + kt);
        asm volatile("cp.async.commit_group;\n");
    };

    load_tile(0, 0);

    for (int it = 0; it < NKITER; it++) {
        if (it + 1 < NKITER) {
            load_tile((it + 1) & 1, (it + 1) * BK);
            asm volatile("cp.async.wait_group 1;\n");
        } else {
            asm volatile("cp.async.wait_group 0;\n");
        }
        __syncthreads();

        const uint32_t bufoff = (uint32_t)(it & 1) * 16384;
#pragma unroll
        for (int ks = 0; ks < 2; ks++) {
            const uint32_t kx = (uint32_t)ks << 5;
            uint32_t a_hi[4][4], a_lo[4][4];
#pragma unroll
            for (int mt = 0; mt < 4; mt++) {
                LDSM4(a_hi[mt], (addrA[0][mt] + bufoff) ^ kx);
                LDSM4(a_lo[mt], (addrA[1][mt] + bufoff) ^ kx);
            }
            uint32_t b_hi[2][4], b_lo[2][4];
#pragma unroll
            for (int p = 0; p < 2; p++) {
                LDSM4(b_hi[p], (addrB[0][p] + bufoff) ^ kx);
                LDSM4(b_lo[p], (addrB[1][p] + bufoff) ^ kx);
            }
#pragma unroll
            for (int mt = 0; mt < 4; mt++)
#pragma unroll
                for (int p = 0; p < 2; p++) {
                    mma_bf16(acc[mt][2 * p],     a_hi[mt], &b_hi[p][0]);
                    mma_bf16(acc[mt][2 * p],     a_hi[mt], &b_lo[p][0]);
                    mma_bf16(acc[mt][2 * p],     a_lo[mt], &b_hi[p][0]);
                    mma_bf16(acc[mt][2 * p + 1], a_hi[mt], &b_hi[p][2]);
                    mma_bf16(acc[mt][2 * p + 1], a_hi[mt], &b_lo[p][2]);
                    mma_bf16(acc[mt][2 * p + 1], a_lo[mt], &b_hi[p][2]);
                }
        }
        __syncthreads();
    }

    // ---- epilogue ----
    const int gp = lane >> 2, tg = lane & 3;
#pragma unroll
    for (int nt = 0; nt < 4; nt++) {
        const int n = bn0 + wn + nt * 8 + tg * 2;
        float b0 = 0.0f, b1 = 0.0f;
        if (bias) { b0 = bias[n]; b1 = bias[n + 1]; }
#pragma unroll
        for (int mt = 0; mt < 4; mt++) {
            const int m = bm0 + wm + mt * 16 + gp;
            float2 o0 = make_float2(acc[mt][nt][0] + b0, acc[mt][nt][1] + b1);
            float2 o1 = make_float2(acc[mt][nt][2] + b0, acc[mt][nt][3] + b1);
            *reinterpret_cast<float2*>(C + (size_t)m * E_DIM + n) = o0;
            *reinterpret_cast<float2*>(C + (size_t)(m + 8) * E_DIM + n) = o1;
        }
    }
}

// -------- closed-form quantum layer, emits (hi,lo) bf16 directly --------
//   theta_j = v[g,j] + rx[j]; c_j = cos(theta_j)
//   q[g,0] = c1..c7;  q[g,w] = c0..cw (w>=1)
__global__ void quantum_kernel(const float* __restrict__ v,
                               const float* __restrict__ rx,
                               __nv_bfloat16* __restrict__ qh,
                               __nv_bfloat16* __restrict__ ql, int n)
{
    int g = blockIdx.x * blockDim.x + threadIdx.x;
    if (g >= n) return;
    const float4* vp = reinterpret_cast<const float4*>(v + (size_t)g * 8);
    float4 v0 = vp[0], v1 = vp[1];

    float c0 = cosf(v0.x + __ldg(rx + 0));
    float c1 = cosf(v0.y + __ldg(rx + 1));
    float c2 = cosf(v0.z + __ldg(rx + 2));
    float c3 = cosf(v0.w + __ldg(rx + 3));
    float c4 = cosf(v1.x + __ldg(rx + 4));
    float c5 = cosf(v1.y + __ldg(rx + 5));
    float c6 = cosf(v1.z + __ldg(rx + 6));
    float c7 = cosf(v1.w + __ldg(rx + 7));

    float p[8];
    p[1] = c0 * c1;
    p[2] = p[1] * c2;
    p[3] = p[2] * c3;
    p[4] = p[3] * c4;
    p[5] = p[4] * c5;
    p[6] = p[5] * c6;
    p[7] = p[6] * c7;
    p[0] = ((c1 * c2) * (c3 * c4)) * ((c5 * c6) * c7);

    __nv_bfloat16 h[8], l[8];
#pragma unroll
    for (int i = 0; i < 8; i++) split_bf(p[i], h[i], l[i]);

    struct alignas(16) bf8 { __nv_bfloat16 x[8]; };
    bf8 H, L;
#pragma unroll
    for (int i = 0; i < 8; i++) { H.x[i] = h[i]; L.x[i] = l[i]; }
    *reinterpret_cast<bf8*>(qh + (size_t)g * 8) = H;
    *reinterpret_cast<bf8*>(ql + (size_t)g * 8) = L;
}

extern "C" void kernel_launch(void* const* d_in, const int* in_sizes, int n_in,
                              void* d_out, int out_size)
{
    const float* x  = (const float*)d_in[0];
    // d_in[1]=wq, d_in[2]=wk unused: S==1 -> softmax==1 -> attention out == v
    const float* wv = (const float*)d_in[3];
    const float* wc = (const float*)d_in[4];
    const float* bc = (const float*)d_in[5];
    const float* rx = (const float*)d_in[6];
    float* out = (float*)d_out;

    __nv_bfloat16 *xh, *xl, *wvh, *wvl, *wch, *wcl, *qh, *ql;
    float* vbuf;
    cudaGetSymbolAddress((void**)&xh,  g_xh);
    cudaGetSymbolAddress((void**)&xl,  g_xl);
    cudaGetSymbolAddress((void**)&wvh, g_wvh);
    cudaGetSymbolAddress((void**)&wvl, g_wvl);
    cudaGetSymbolAddress((void**)&wch, g_wch);
    cudaGetSymbolAddress((void**)&wcl, g_wcl);
    cudaGetSymbolAddress((void**)&qh,  g_qh);
    cudaGetSymbolAddress((void**)&ql,  g_ql);
    cudaGetSymbolAddress((void**)&vbuf, g_v);

    cudaFuncSetAttribute(gemm_bf16x3, cudaFuncAttributeMaxDynamicSharedMemorySize, 65536);

    // split inputs into bf16 hi/lo
    split_kernel<<<(M_DIM * E_DIM / 4 + 255) / 256, 256>>>(x, xh, xl, M_DIM * E_DIM / 4);
    split_kernel<<<(E_DIM * E_DIM / 4 + 255) / 256, 256>>>(wv, wvh, wvl, E_DIM * E_DIM / 4);
    split_kernel<<<(E_DIM * E_DIM / 4 + 255) / 256, 256>>>(wc, wch, wcl, E_DIM * E_DIM / 4);

    dim3 grid(E_DIM / BN, M_DIM / BM);
    // v = x @ wv^T
    gemm_bf16x3<<<grid, 256, 65536>>>(xh, xl, wvh, wvl, nullptr, vbuf);
    // closed-form quantum layer
    quantum_kernel<<<NGROUPS / 256, 256>>>(vbuf, rx, qh, ql, NGROUPS);
    // out = q @ wc^T + bc
    gemm_bf16x3<<<grid, 256, 65536>>>(qh, ql, wch, wcl, bc, out);
}